// round 1
// baseline (speedup 1.0000x reference)
#include <cuda_runtime.h>
#include <cstdint>

// Problem constants
#define N_USERS  40000
#define N_ITEMS  60000
#define NTOT     100000
#define IN_DIM   128
#define HID      256
#define OUT_DIM  256
#define N_EDGES  600000

// Scratch (allocation-free rule: device globals)
__device__ float g_x [(size_t)NTOT * HID];   // feat @ W0 + b0
__device__ float g_h [(size_t)NTOT * HID];   // feat @ Wres0, then += spmm(x)
__device__ float g_x2[(size_t)NTOT * OUT_DIM]; // relu(h) @ W1 + b1

// ---------------------------------------------------------------------------
// GEMM0 (dual): x = feat @ W0 + b0 ; h = feat @ Wres0
// feat rows come from user_feat (rows < N_USERS) or item_feat.
// BM=128, BN=64, BK=16, 256 threads, thread tile 8x4, dual accumulators.
// ---------------------------------------------------------------------------
__global__ __launch_bounds__(256) void gemm0_dual(
    const float* __restrict__ uf, const float* __restrict__ itf,
    const float* __restrict__ W0, const float* __restrict__ b0,
    const float* __restrict__ Wres)
{
    const int BM = 128, BN = 64, BK = 16;
    __shared__ float As [BK][BM];
    __shared__ float Bs0[BK][BN];
    __shared__ float Bs1[BK][BN];

    const int bm = blockIdx.x * BM;
    const int bn = blockIdx.y * BN;
    const int tid = threadIdx.x;

    // A-load mapping: 256 threads, 128 rows x 16 K = 2048 floats -> 2 float4/thread
    const int a_m = tid >> 1;             // 0..127
    const int a_k = (tid & 1) * 8;        // 0 or 8
    // W-load mapping: 16 x 64 = 1024 floats -> 1 float4/thread
    const int w_k = tid >> 4;             // 0..15
    const int w_n = (tid & 15) * 4;       // 0..60

    const int ty = tid >> 4;              // 0..15 -> rows ty*8..+7
    const int tx = tid & 15;              // 0..15 -> cols tx*4..+3

    float acc0[8][4]; float acc1[8][4];
    #pragma unroll
    for (int i = 0; i < 8; i++)
        #pragma unroll
        for (int j = 0; j < 4; j++) { acc0[i][j] = 0.f; acc1[i][j] = 0.f; }

    const int row = bm + a_m;
    const float* rp = nullptr;
    if (row < NTOT)
        rp = (row < N_USERS) ? (uf + (size_t)row * IN_DIM)
                             : (itf + (size_t)(row - N_USERS) * IN_DIM);

    for (int k0 = 0; k0 < IN_DIM; k0 += BK) {
        // load A tile (transposed into As[k][m])
        float4 av0 = make_float4(0.f,0.f,0.f,0.f);
        float4 av1 = make_float4(0.f,0.f,0.f,0.f);
        if (rp) {
            av0 = *(const float4*)(rp + k0 + a_k);
            av1 = *(const float4*)(rp + k0 + a_k + 4);
        }
        As[a_k+0][a_m] = av0.x; As[a_k+1][a_m] = av0.y;
        As[a_k+2][a_m] = av0.z; As[a_k+3][a_m] = av0.w;
        As[a_k+4][a_m] = av1.x; As[a_k+5][a_m] = av1.y;
        As[a_k+6][a_m] = av1.z; As[a_k+7][a_m] = av1.w;
        // load W tiles
        *(float4*)&Bs0[w_k][w_n] = *(const float4*)(W0   + (size_t)(k0 + w_k) * HID + bn + w_n);
        *(float4*)&Bs1[w_k][w_n] = *(const float4*)(Wres + (size_t)(k0 + w_k) * HID + bn + w_n);
        __syncthreads();

        #pragma unroll
        for (int k = 0; k < BK; k++) {
            float a[8], p0[4], p1[4];
            #pragma unroll
            for (int i = 0; i < 8; i++) a[i] = As[k][ty*8 + i];
            float4 q0 = *(float4*)&Bs0[k][tx*4];
            float4 q1 = *(float4*)&Bs1[k][tx*4];
            p0[0]=q0.x; p0[1]=q0.y; p0[2]=q0.z; p0[3]=q0.w;
            p1[0]=q1.x; p1[1]=q1.y; p1[2]=q1.z; p1[3]=q1.w;
            #pragma unroll
            for (int i = 0; i < 8; i++)
                #pragma unroll
                for (int j = 0; j < 4; j++) {
                    acc0[i][j] += a[i] * p0[j];
                    acc1[i][j] += a[i] * p1[j];
                }
        }
        __syncthreads();
    }

    const int rbase = bm + ty*8;
    const int cbase = bn + tx*4;
    float bias[4];
    #pragma unroll
    for (int j = 0; j < 4; j++) bias[j] = b0[cbase + j];
    #pragma unroll
    for (int i = 0; i < 8; i++) {
        int r = rbase + i;
        if (r < NTOT) {
            #pragma unroll
            for (int j = 0; j < 4; j++) {
                g_x[(size_t)r * HID + cbase + j] = acc0[i][j] + bias[j];
                g_h[(size_t)r * HID + cbase + j] = acc1[i][j];
            }
        }
    }
}

// ---------------------------------------------------------------------------
// GEMM1: x2 = relu(h) @ W1 + b1   (K = 256)
// ---------------------------------------------------------------------------
__global__ __launch_bounds__(256) void gemm1_relu(
    const float* __restrict__ W1, const float* __restrict__ b1)
{
    const int BM = 128, BN = 64, BK = 16;
    __shared__ float As[BK][BM];
    __shared__ float Bs[BK][BN];

    const int bm = blockIdx.x * BM;
    const int bn = blockIdx.y * BN;
    const int tid = threadIdx.x;

    const int a_m = tid >> 1;
    const int a_k = (tid & 1) * 8;
    const int w_k = tid >> 4;
    const int w_n = (tid & 15) * 4;
    const int ty = tid >> 4;
    const int tx = tid & 15;

    float acc[8][4];
    #pragma unroll
    for (int i = 0; i < 8; i++)
        #pragma unroll
        for (int j = 0; j < 4; j++) acc[i][j] = 0.f;

    const int row = bm + a_m;
    const bool rok = row < NTOT;
    const float* rp = g_h + (size_t)row * HID;

    for (int k0 = 0; k0 < HID; k0 += BK) {
        float4 av0 = make_float4(0.f,0.f,0.f,0.f);
        float4 av1 = make_float4(0.f,0.f,0.f,0.f);
        if (rok) {
            av0 = *(const float4*)(rp + k0 + a_k);
            av1 = *(const float4*)(rp + k0 + a_k + 4);
        }
        // fuse relu on the A operand
        As[a_k+0][a_m] = fmaxf(av0.x, 0.f); As[a_k+1][a_m] = fmaxf(av0.y, 0.f);
        As[a_k+2][a_m] = fmaxf(av0.z, 0.f); As[a_k+3][a_m] = fmaxf(av0.w, 0.f);
        As[a_k+4][a_m] = fmaxf(av1.x, 0.f); As[a_k+5][a_m] = fmaxf(av1.y, 0.f);
        As[a_k+6][a_m] = fmaxf(av1.z, 0.f); As[a_k+7][a_m] = fmaxf(av1.w, 0.f);
        *(float4*)&Bs[w_k][w_n] = *(const float4*)(W1 + (size_t)(k0 + w_k) * OUT_DIM + bn + w_n);
        __syncthreads();

        #pragma unroll
        for (int k = 0; k < BK; k++) {
            float a[8];
            #pragma unroll
            for (int i = 0; i < 8; i++) a[i] = As[k][ty*8 + i];
            float4 q = *(float4*)&Bs[k][tx*4];
            float p[4] = {q.x, q.y, q.z, q.w};
            #pragma unroll
            for (int i = 0; i < 8; i++)
                #pragma unroll
                for (int j = 0; j < 4; j++)
                    acc[i][j] += a[i] * p[j];
        }
        __syncthreads();
    }

    const int rbase = bm + ty*8;
    const int cbase = bn + tx*4;
    float bias[4];
    #pragma unroll
    for (int j = 0; j < 4; j++) bias[j] = b1[cbase + j];
    #pragma unroll
    for (int i = 0; i < 8; i++) {
        int r = rbase + i;
        if (r < NTOT) {
            #pragma unroll
            for (int j = 0; j < 4; j++)
                g_x2[(size_t)r * OUT_DIM + cbase + j] = acc[i][j] + bias[j];
        }
    }
}

// ---------------------------------------------------------------------------
// SpMM: Y[rows[e]] += vals[e] * X[cols[e]]  (one warp per edge, 8 f32/lane)
// ---------------------------------------------------------------------------
__global__ __launch_bounds__(256) void spmm_atomic(
    const int* __restrict__ rows, const int* __restrict__ cols,
    const float* __restrict__ vals, const float* __restrict__ X,
    float* __restrict__ Y)
{
    int e = blockIdx.x * 8 + (threadIdx.x >> 5);
    if (e >= N_EDGES) return;
    const int lane = threadIdx.x & 31;
    const int r = rows[e];
    const int c = cols[e];
    const float v = vals[e];
    const float* xp = X + (size_t)c * 256;
    float* yp = Y + (size_t)r * 256;
    #pragma unroll
    for (int j = 0; j < 8; j++) {
        atomicAdd(yp + j*32 + lane, v * __ldg(xp + j*32 + lane));
    }
}

// ---------------------------------------------------------------------------
extern "C" void kernel_launch(void* const* d_in, const int* in_sizes, int n_in,
                              void* d_out, int out_size)
{
    const float* user_feat = (const float*)d_in[0];
    const float* item_feat = (const float*)d_in[1];
    const int*   edge_rows = (const int*)  d_in[2];
    const int*   edge_cols = (const int*)  d_in[3];
    const float* edge_vals = (const float*)d_in[4];
    const float* W0        = (const float*)d_in[5];
    const float* b0        = (const float*)d_in[6];
    const float* Wres0     = (const float*)d_in[7];
    const float* W1        = (const float*)d_in[8];
    const float* b1        = (const float*)d_in[9];
    float* out = (float*)d_out;

    float* gx;  cudaGetSymbolAddress((void**)&gx,  g_x);
    float* gh;  cudaGetSymbolAddress((void**)&gh,  g_h);
    float* gx2; cudaGetSymbolAddress((void**)&gx2, g_x2);

    dim3 gemm_grid((NTOT + 127) / 128, HID / 64);

    // Layer 0: x = feat@W0+b0 ; h = feat@Wres0
    gemm0_dual<<<gemm_grid, 256>>>(user_feat, item_feat, W0, b0, Wres0);

    // zero the final output early (memset node), independent of pipeline order
    cudaMemsetAsync(d_out, 0, (size_t)NTOT * OUT_DIM * sizeof(float));

    // h += A @ x
    spmm_atomic<<<(N_EDGES + 7) / 8, 256>>>(edge_rows, edge_cols, edge_vals, gx, gh);

    // Layer 1: x2 = relu(h)@W1 + b1
    gemm1_relu<<<gemm_grid, 256>>>(W1, b1);

    // out = A @ x2
    spmm_atomic<<<(N_EDGES + 7) / 8, 256>>>(edge_rows, edge_cols, edge_vals, gx2, out);
}

// round 3
// speedup vs baseline: 1.1585x; 1.1585x over previous
#include <cuda_runtime.h>
#include <cstdint>

#define N_USERS  40000
#define NTOT     100000
#define IN_DIM   128
#define HID      256
#define OUT_DIM  256
#define N_EDGES  600000

// Scratch (allocation-free rule: device globals)
__device__ float g_x  [(size_t)NTOT * HID];     // feat @ W0 + b0
__device__ float g_h  [(size_t)NTOT * HID];     // feat @ Wres0 + spmm(x)
__device__ float g_x2 [(size_t)NTOT * OUT_DIM]; // relu(h) @ W1 + b1
__device__ float g_W01T[512 * IN_DIM];          // [W0^T ; Wres^T]  rows=n(512), cols=k(128), tf32
__device__ float g_W1T [OUT_DIM * HID];         // W1^T [256][256], tf32

__device__ __forceinline__ float to_tf32(float x) {
    uint32_t u;
    asm("cvt.rna.tf32.f32 %0, %1;" : "=r"(u) : "f"(x));
    return __uint_as_float(u);
}
__device__ __forceinline__ void mma_tf32(float* c, const uint32_t* a, const uint32_t* b) {
    asm volatile(
        "mma.sync.aligned.m16n8k8.row.col.f32.tf32.tf32.f32 "
        "{%0,%1,%2,%3}, {%4,%5,%6,%7}, {%8,%9}, {%0,%1,%2,%3};"
        : "+f"(c[0]), "+f"(c[1]), "+f"(c[2]), "+f"(c[3])
        : "r"(a[0]), "r"(a[1]), "r"(a[2]), "r"(a[3]), "r"(b[0]), "r"(b[1]));
}

#define PAD 36  // floats per smem row: lane bank = (l>>2)*4 + (l&3) -> conflict-free frags

// ---------------------------------------------------------------------------
// Weight transpose + tf32 pre-round:  [K,N] row-major -> [N,K]
// ---------------------------------------------------------------------------
__global__ void transpose_weights(const float* __restrict__ W0,
                                  const float* __restrict__ Wres,
                                  const float* __restrict__ W1) {
    int idx = blockIdx.x * 256 + threadIdx.x;
    if (idx < IN_DIM * HID) {
        int k = idx / HID, n = idx % HID;
        g_W01T[n * IN_DIM + k]         = to_tf32(W0[idx]);
        g_W01T[(n + 256) * IN_DIM + k] = to_tf32(Wres[idx]);
    }
    if (idx < HID * OUT_DIM) {
        int k = idx / OUT_DIM, n = idx % OUT_DIM;
        g_W1T[n * HID + k] = to_tf32(W1[idx]);
    }
}

// ---------------------------------------------------------------------------
// GEMM0 (tf32 mma): [x | h] = feat @ [W0 | Wres] (+b0 on x half)
// BM=128, BN=128 (blockIdx.y in 0..3 over N=512), BK=32.
// 8 warps: warp_m = wid&3 (32 rows), warp_n = wid>>2 (64 cols).
// ---------------------------------------------------------------------------
__global__ __launch_bounds__(256, 2) void gemm0_mma(
    const float* __restrict__ uf, const float* __restrict__ itf,
    const float* __restrict__ b0)
{
    __shared__ float As[128][PAD];
    __shared__ float Bs[128][PAD];
    const int tid = threadIdx.x, lane = tid & 31, wid = tid >> 5;
    const int wm = (wid & 3) * 32, wn = (wid >> 2) * 64;
    const int bm = blockIdx.x * 128;
    const int nblk = blockIdx.y;                 // 0..3
    const float* WT = g_W01T + (size_t)nblk * 128 * IN_DIM;
    const int g = lane >> 2, t = lane & 3;

    float acc[2][8][4];
    #pragma unroll
    for (int i = 0; i < 2; i++)
        #pragma unroll
        for (int j = 0; j < 8; j++)
            #pragma unroll
            for (int q = 0; q < 4; q++) acc[i][j][q] = 0.f;

    for (int ck = 0; ck < IN_DIM / 32; ck++) {
        const int k0 = ck * 32;
        #pragma unroll
        for (int i = 0; i < 4; i++) {           // A tile: 128x32
            int f = i * 256 + tid;
            int r = f >> 3, c4 = (f & 7) * 4;
            float4 v = make_float4(0.f, 0.f, 0.f, 0.f);
            int rg = bm + r;
            if (rg < NTOT) {
                const float* rp = (rg < N_USERS) ? uf + (size_t)rg * IN_DIM
                                                 : itf + (size_t)(rg - N_USERS) * IN_DIM;
                v = *(const float4*)(rp + k0 + c4);
            }
            As[r][c4 + 0] = to_tf32(v.x); As[r][c4 + 1] = to_tf32(v.y);
            As[r][c4 + 2] = to_tf32(v.z); As[r][c4 + 3] = to_tf32(v.w);
        }
        #pragma unroll
        for (int i = 0; i < 4; i++) {           // B tile: 128x32 (already tf32)
            int f = i * 256 + tid;
            int r = f >> 3, c4 = (f & 7) * 4;
            float4 v = *(const float4*)(WT + (size_t)r * IN_DIM + k0 + c4);
            Bs[r][c4 + 0] = v.x; Bs[r][c4 + 1] = v.y;
            Bs[r][c4 + 2] = v.z; Bs[r][c4 + 3] = v.w;
        }
        __syncthreads();

        #pragma unroll
        for (int kk = 0; kk < 4; kk++) {
            const int kb = kk * 8;
            uint32_t a[2][4];
            #pragma unroll
            for (int fm = 0; fm < 2; fm++) {
                int r0 = wm + fm * 16 + g;
                a[fm][0] = __float_as_uint(As[r0    ][kb + t]);
                a[fm][1] = __float_as_uint(As[r0 + 8][kb + t]);
                a[fm][2] = __float_as_uint(As[r0    ][kb + t + 4]);
                a[fm][3] = __float_as_uint(As[r0 + 8][kb + t + 4]);
            }
            #pragma unroll
            for (int nf = 0; nf < 8; nf++) {
                uint32_t b[2];
                int rn = wn + nf * 8 + g;
                b[0] = __float_as_uint(Bs[rn][kb + t]);
                b[1] = __float_as_uint(Bs[rn][kb + t + 4]);
                mma_tf32(acc[0][nf], a[0], b);
                mma_tf32(acc[1][nf], a[1], b);
            }
        }
        __syncthreads();
    }

    float* dst = (nblk < 2) ? g_x : g_h;
    const bool addb = (nblk < 2);
    const int cbase = (nblk & 1) * 128 + wn;
    #pragma unroll
    for (int fm = 0; fm < 2; fm++) {
        int row = bm + wm + fm * 16 + g;
        #pragma unroll
        for (int nf = 0; nf < 8; nf++) {
            int col = cbase + nf * 8 + 2 * t;
            float bv0 = 0.f, bv1 = 0.f;
            if (addb) { bv0 = __ldg(b0 + col); bv1 = __ldg(b0 + col + 1); }
            if (row < NTOT)
                *(float2*)(dst + (size_t)row * 256 + col) =
                    make_float2(acc[fm][nf][0] + bv0, acc[fm][nf][1] + bv1);
            if (row + 8 < NTOT)
                *(float2*)(dst + (size_t)(row + 8) * 256 + col) =
                    make_float2(acc[fm][nf][2] + bv0, acc[fm][nf][3] + bv1);
        }
    }
}

// ---------------------------------------------------------------------------
// GEMM1 (tf32 mma): x2 = relu(h) @ W1 + b1.   K=256, N=256 (blockIdx.y 0..1)
// ---------------------------------------------------------------------------
__global__ __launch_bounds__(256, 2) void gemm1_mma(const float* __restrict__ b1)
{
    __shared__ float As[128][PAD];
    __shared__ float Bs[128][PAD];
    const int tid = threadIdx.x, lane = tid & 31, wid = tid >> 5;
    const int wm = (wid & 3) * 32, wn = (wid >> 2) * 64;
    const int bm = blockIdx.x * 128;
    const int nblk = blockIdx.y;                 // 0..1
    const int g = lane >> 2, t = lane & 3;

    float acc[2][8][4];
    #pragma unroll
    for (int i = 0; i < 2; i++)
        #pragma unroll
        for (int j = 0; j < 8; j++)
            #pragma unroll
            for (int q = 0; q < 4; q++) acc[i][j][q] = 0.f;

    for (int ck = 0; ck < HID / 32; ck++) {
        const int k0 = ck * 32;
        #pragma unroll
        for (int i = 0; i < 4; i++) {           // A: relu(g_h) 128x32
            int f = i * 256 + tid;
            int r = f >> 3, c4 = (f & 7) * 4;
            float4 v = make_float4(0.f, 0.f, 0.f, 0.f);
            int rg = bm + r;
            if (rg < NTOT)
                v = *(const float4*)(g_h + (size_t)rg * HID + k0 + c4);
            As[r][c4 + 0] = to_tf32(fmaxf(v.x, 0.f));
            As[r][c4 + 1] = to_tf32(fmaxf(v.y, 0.f));
            As[r][c4 + 2] = to_tf32(fmaxf(v.z, 0.f));
            As[r][c4 + 3] = to_tf32(fmaxf(v.w, 0.f));
        }
        #pragma unroll
        for (int i = 0; i < 4; i++) {           // B: g_W1T rows nblk*128..
            int f = i * 256 + tid;
            int r = f >> 3, c4 = (f & 7) * 4;
            float4 v = *(const float4*)(g_W1T + (size_t)(nblk * 128 + r) * HID + k0 + c4);
            Bs[r][c4 + 0] = v.x; Bs[r][c4 + 1] = v.y;
            Bs[r][c4 + 2] = v.z; Bs[r][c4 + 3] = v.w;
        }
        __syncthreads();

        #pragma unroll
        for (int kk = 0; kk < 4; kk++) {
            const int kb = kk * 8;
            uint32_t a[2][4];
            #pragma unroll
            for (int fm = 0; fm < 2; fm++) {
                int r0 = wm + fm * 16 + g;
                a[fm][0] = __float_as_uint(As[r0    ][kb + t]);
                a[fm][1] = __float_as_uint(As[r0 + 8][kb + t]);
                a[fm][2] = __float_as_uint(As[r0    ][kb + t + 4]);
                a[fm][3] = __float_as_uint(As[r0 + 8][kb + t + 4]);
            }
            #pragma unroll
            for (int nf = 0; nf < 8; nf++) {
                uint32_t b[2];
                int rn = wn + nf * 8 + g;
                b[0] = __float_as_uint(Bs[rn][kb + t]);
                b[1] = __float_as_uint(Bs[rn][kb + t + 4]);
                mma_tf32(acc[0][nf], a[0], b);
                mma_tf32(acc[1][nf], a[1], b);
            }
        }
        __syncthreads();
    }

    const int cbase = nblk * 128 + wn;
    #pragma unroll
    for (int fm = 0; fm < 2; fm++) {
        int row = bm + wm + fm * 16 + g;
        #pragma unroll
        for (int nf = 0; nf < 8; nf++) {
            int col = cbase + nf * 8 + 2 * t;
            float bv0 = __ldg(b1 + col), bv1 = __ldg(b1 + col + 1);
            if (row < NTOT)
                *(float2*)(g_x2 + (size_t)row * 256 + col) =
                    make_float2(acc[fm][nf][0] + bv0, acc[fm][nf][1] + bv1);
            if (row + 8 < NTOT)
                *(float2*)(g_x2 + (size_t)(row + 8) * 256 + col) =
                    make_float2(acc[fm][nf][2] + bv0, acc[fm][nf][3] + bv1);
        }
    }
}

// ---------------------------------------------------------------------------
// SpMM pass: Y[rows[e]] += vals[e] * X[cols[e]] for edges whose (row,col) fall
// in the given ranges. One warp per edge, 8 f32 atomics/lane.
// ---------------------------------------------------------------------------
__global__ __launch_bounds__(256) void spmm_part(
    const int* __restrict__ rows, const int* __restrict__ cols,
    const float* __restrict__ vals, const float* __restrict__ X,
    float* __restrict__ Y, int rlo, int rhi, int clo, int chi)
{
    int e = blockIdx.x * 8 + (threadIdx.x >> 5);
    if (e >= N_EDGES) return;
    const int r = rows[e];
    const int c = cols[e];
    if (r < rlo || r >= rhi || c < clo || c >= chi) return;
    const int lane = threadIdx.x & 31;
    const float v = vals[e];
    const float* xp = X + (size_t)c * 256;
    float* yp = Y + (size_t)r * 256;
    #pragma unroll
    for (int j = 0; j < 8; j++)
        atomicAdd(yp + j * 32 + lane, v * __ldg(xp + j * 32 + lane));
}

static inline void spmm4(const int* rows, const int* cols, const float* vals,
                         const float* X, float* Y)
{
    const int H = NTOT / 2;  // 50000
    const int nb = (N_EDGES + 7) / 8;
    // gray order: keep one half resident between consecutive passes
    spmm_part<<<nb, 256>>>(rows, cols, vals, X, Y, 0, H, 0, H);
    spmm_part<<<nb, 256>>>(rows, cols, vals, X, Y, H, NTOT, 0, H);
    spmm_part<<<nb, 256>>>(rows, cols, vals, X, Y, H, NTOT, H, NTOT);
    spmm_part<<<nb, 256>>>(rows, cols, vals, X, Y, 0, H, H, NTOT);
}

// ---------------------------------------------------------------------------
extern "C" void kernel_launch(void* const* d_in, const int* in_sizes, int n_in,
                              void* d_out, int out_size)
{
    const float* user_feat = (const float*)d_in[0];
    const float* item_feat = (const float*)d_in[1];
    const int*   edge_rows = (const int*)  d_in[2];
    const int*   edge_cols = (const int*)  d_in[3];
    const float* edge_vals = (const float*)d_in[4];
    const float* W0        = (const float*)d_in[5];
    const float* b0        = (const float*)d_in[6];
    const float* Wres0     = (const float*)d_in[7];
    const float* W1        = (const float*)d_in[8];
    const float* b1        = (const float*)d_in[9];
    float* out = (float*)d_out;

    float* gx;  cudaGetSymbolAddress((void**)&gx,  g_x);
    float* gh;  cudaGetSymbolAddress((void**)&gh,  g_h);
    float* gx2; cudaGetSymbolAddress((void**)&gx2, g_x2);

    const int n_mtiles = (NTOT + 127) / 128;  // 782

    // weights -> K-major tf32 transposed copies
    transpose_weights<<<(HID * OUT_DIM + 255) / 256, 256>>>(W0, Wres0, W1);

    // Layer 0: x = feat@W0+b0 ; h = feat@Wres0   (N=512 fused)
    gemm0_mma<<<dim3(n_mtiles, 4), 256>>>(user_feat, item_feat, b0);

    // zero final output (independent memset node)
    cudaMemsetAsync(d_out, 0, (size_t)NTOT * OUT_DIM * sizeof(float));

    // h += A @ x
    spmm4(edge_rows, edge_cols, edge_vals, gx, gh);

    // Layer 1: x2 = relu(h)@W1 + b1
    gemm1_mma<<<dim3(n_mtiles, 2), 256>>>(b1);

    // out = A @ x2
    spmm4(edge_rows, edge_cols, edge_vals, gx2, out);
}

// round 4
// speedup vs baseline: 1.6761x; 1.4468x over previous
#include <cuda_runtime.h>
#include <cstdint>

#define N_USERS  40000
#define NTOT     100000
#define IN_DIM   128
#define HID      256
#define OUT_DIM  256
#define N_EDGES  600000

#define BSHIFT   6
#define NBUCK    ((NTOT + 63) >> BSHIFT)   // 1563
#define SCAN_N   2048

// Scratch (allocation-free rule: device globals)
__device__ float g_x  [(size_t)NTOT * HID];
__device__ float g_h  [(size_t)NTOT * HID];
__device__ float g_x2 [(size_t)NTOT * OUT_DIM];
__device__ float g_W01T[512 * IN_DIM];          // [W0^T ; Wres^T], tf32
__device__ float g_W1T [OUT_DIM * HID];         // W1^T, tf32
__device__ int   g_cnt [NBUCK];
__device__ int   g_cnt2[NBUCK];
__device__ int   g_off [NBUCK];
__device__ int   g_srow[N_EDGES];
__device__ int   g_scol[N_EDGES];
__device__ float g_sval[N_EDGES];

__device__ __forceinline__ float to_tf32(float x) {
    uint32_t u;
    asm("cvt.rna.tf32.f32 %0, %1;" : "=r"(u) : "f"(x));
    return __uint_as_float(u);
}
__device__ __forceinline__ void mma_tf32(float* c, const uint32_t* a, const uint32_t* b) {
    asm volatile(
        "mma.sync.aligned.m16n8k8.row.col.f32.tf32.tf32.f32 "
        "{%0,%1,%2,%3}, {%4,%5,%6,%7}, {%8,%9}, {%0,%1,%2,%3};"
        : "+f"(c[0]), "+f"(c[1]), "+f"(c[2]), "+f"(c[3])
        : "r"(a[0]), "r"(a[1]), "r"(a[2]), "r"(a[3]), "r"(b[0]), "r"(b[1]));
}

#define PAD 36

// ---------------------------------------------------------------------------
// Weight transpose + tf32 pre-round
// ---------------------------------------------------------------------------
__global__ void transpose_weights(const float* __restrict__ W0,
                                  const float* __restrict__ Wres,
                                  const float* __restrict__ W1) {
    int idx = blockIdx.x * 256 + threadIdx.x;
    if (idx < IN_DIM * HID) {
        int k = idx / HID, n = idx % HID;
        g_W01T[n * IN_DIM + k]         = to_tf32(W0[idx]);
        g_W01T[(n + 256) * IN_DIM + k] = to_tf32(Wres[idx]);
    }
    if (idx < HID * OUT_DIM) {
        int k = idx / OUT_DIM, n = idx % OUT_DIM;
        g_W1T[n * HID + k] = to_tf32(W1[idx]);
    }
}

// ---------------------------------------------------------------------------
// Edge counting-sort by row bucket (row >> 6)
// ---------------------------------------------------------------------------
__global__ __launch_bounds__(256) void edge_hist(const int* __restrict__ rows) {
    int e = blockIdx.x * 256 + threadIdx.x;
    if (e < N_EDGES) atomicAdd(&g_cnt[rows[e] >> BSHIFT], 1);
}

__global__ __launch_bounds__(1024) void bucket_scan() {
    __shared__ int s[2][SCAN_N];
    const int tid = threadIdx.x;
    // exclusive scan: s[i] = sum of cnt[0..i-1]
    #pragma unroll
    for (int i = tid; i < SCAN_N; i += 1024)
        s[0][i] = (i > 0 && i - 1 < NBUCK) ? g_cnt[i - 1] : 0;
    __syncthreads();
    int p = 0;
    #pragma unroll
    for (int d = 1; d < SCAN_N; d <<= 1) {
        #pragma unroll
        for (int i = tid; i < SCAN_N; i += 1024)
            s[p ^ 1][i] = s[p][i] + ((i >= d) ? s[p][i - d] : 0);
        p ^= 1;
        __syncthreads();
    }
    #pragma unroll
    for (int i = tid; i < SCAN_N; i += 1024)
        if (i < NBUCK) g_off[i] = s[p][i];
}

__global__ __launch_bounds__(256) void edge_scatter(
    const int* __restrict__ rows, const int* __restrict__ cols,
    const float* __restrict__ vals) {
    int e = blockIdx.x * 256 + threadIdx.x;
    if (e >= N_EDGES) return;
    int r = rows[e];
    int b = r >> BSHIFT;
    int pos = g_off[b] + atomicAdd(&g_cnt2[b], 1);
    g_srow[pos] = r;
    g_scol[pos] = cols[e];
    g_sval[pos] = vals[e];
}

// ---------------------------------------------------------------------------
// GEMM0 (tf32 mma): [x | h] = feat @ [W0 | Wres] (+b0 on x half)
// ---------------------------------------------------------------------------
__global__ __launch_bounds__(256, 2) void gemm0_mma(
    const float* __restrict__ uf, const float* __restrict__ itf,
    const float* __restrict__ b0)
{
    __shared__ float As[128][PAD];
    __shared__ float Bs[128][PAD];
    const int tid = threadIdx.x, lane = tid & 31, wid = tid >> 5;
    const int wm = (wid & 3) * 32, wn = (wid >> 2) * 64;
    const int bm = blockIdx.x * 128;
    const int nblk = blockIdx.y;
    const float* WT = g_W01T + (size_t)nblk * 128 * IN_DIM;
    const int g = lane >> 2, t = lane & 3;

    float acc[2][8][4];
    #pragma unroll
    for (int i = 0; i < 2; i++)
        #pragma unroll
        for (int j = 0; j < 8; j++)
            #pragma unroll
            for (int q = 0; q < 4; q++) acc[i][j][q] = 0.f;

    for (int ck = 0; ck < IN_DIM / 32; ck++) {
        const int k0 = ck * 32;
        #pragma unroll
        for (int i = 0; i < 4; i++) {
            int f = i * 256 + tid;
            int r = f >> 3, c4 = (f & 7) * 4;
            float4 v = make_float4(0.f, 0.f, 0.f, 0.f);
            int rg = bm + r;
            if (rg < NTOT) {
                const float* rp = (rg < N_USERS) ? uf + (size_t)rg * IN_DIM
                                                 : itf + (size_t)(rg - N_USERS) * IN_DIM;
                v = *(const float4*)(rp + k0 + c4);
            }
            As[r][c4 + 0] = to_tf32(v.x); As[r][c4 + 1] = to_tf32(v.y);
            As[r][c4 + 2] = to_tf32(v.z); As[r][c4 + 3] = to_tf32(v.w);
        }
        #pragma unroll
        for (int i = 0; i < 4; i++) {
            int f = i * 256 + tid;
            int r = f >> 3, c4 = (f & 7) * 4;
            float4 v = *(const float4*)(WT + (size_t)r * IN_DIM + k0 + c4);
            Bs[r][c4 + 0] = v.x; Bs[r][c4 + 1] = v.y;
            Bs[r][c4 + 2] = v.z; Bs[r][c4 + 3] = v.w;
        }
        __syncthreads();

        #pragma unroll
        for (int kk = 0; kk < 4; kk++) {
            const int kb = kk * 8;
            uint32_t a[2][4];
            #pragma unroll
            for (int fm = 0; fm < 2; fm++) {
                int r0 = wm + fm * 16 + g;
                a[fm][0] = __float_as_uint(As[r0    ][kb + t]);
                a[fm][1] = __float_as_uint(As[r0 + 8][kb + t]);
                a[fm][2] = __float_as_uint(As[r0    ][kb + t + 4]);
                a[fm][3] = __float_as_uint(As[r0 + 8][kb + t + 4]);
            }
            #pragma unroll
            for (int nf = 0; nf < 8; nf++) {
                uint32_t b[2];
                int rn = wn + nf * 8 + g;
                b[0] = __float_as_uint(Bs[rn][kb + t]);
                b[1] = __float_as_uint(Bs[rn][kb + t + 4]);
                mma_tf32(acc[0][nf], a[0], b);
                mma_tf32(acc[1][nf], a[1], b);
            }
        }
        __syncthreads();
    }

    float* dst = (nblk < 2) ? g_x : g_h;
    const bool addb = (nblk < 2);
    const int cbase = (nblk & 1) * 128 + wn;
    #pragma unroll
    for (int fm = 0; fm < 2; fm++) {
        int row = bm + wm + fm * 16 + g;
        #pragma unroll
        for (int nf = 0; nf < 8; nf++) {
            int col = cbase + nf * 8 + 2 * t;
            float bv0 = 0.f, bv1 = 0.f;
            if (addb) { bv0 = __ldg(b0 + col); bv1 = __ldg(b0 + col + 1); }
            if (row < NTOT)
                *(float2*)(dst + (size_t)row * 256 + col) =
                    make_float2(acc[fm][nf][0] + bv0, acc[fm][nf][1] + bv1);
            if (row + 8 < NTOT)
                *(float2*)(dst + (size_t)(row + 8) * 256 + col) =
                    make_float2(acc[fm][nf][2] + bv0, acc[fm][nf][3] + bv1);
        }
    }
}

// ---------------------------------------------------------------------------
// GEMM1 (tf32 mma): x2 = relu(h) @ W1 + b1
// ---------------------------------------------------------------------------
__global__ __launch_bounds__(256, 2) void gemm1_mma(const float* __restrict__ b1)
{
    __shared__ float As[128][PAD];
    __shared__ float Bs[128][PAD];
    const int tid = threadIdx.x, lane = tid & 31, wid = tid >> 5;
    const int wm = (wid & 3) * 32, wn = (wid >> 2) * 64;
    const int bm = blockIdx.x * 128;
    const int nblk = blockIdx.y;
    const int g = lane >> 2, t = lane & 3;

    float acc[2][8][4];
    #pragma unroll
    for (int i = 0; i < 2; i++)
        #pragma unroll
        for (int j = 0; j < 8; j++)
            #pragma unroll
            for (int q = 0; q < 4; q++) acc[i][j][q] = 0.f;

    for (int ck = 0; ck < HID / 32; ck++) {
        const int k0 = ck * 32;
        #pragma unroll
        for (int i = 0; i < 4; i++) {
            int f = i * 256 + tid;
            int r = f >> 3, c4 = (f & 7) * 4;
            float4 v = make_float4(0.f, 0.f, 0.f, 0.f);
            int rg = bm + r;
            if (rg < NTOT)
                v = *(const float4*)(g_h + (size_t)rg * HID + k0 + c4);
            As[r][c4 + 0] = to_tf32(fmaxf(v.x, 0.f));
            As[r][c4 + 1] = to_tf32(fmaxf(v.y, 0.f));
            As[r][c4 + 2] = to_tf32(fmaxf(v.z, 0.f));
            As[r][c4 + 3] = to_tf32(fmaxf(v.w, 0.f));
        }
        #pragma unroll
        for (int i = 0; i < 4; i++) {
            int f = i * 256 + tid;
            int r = f >> 3, c4 = (f & 7) * 4;
            float4 v = *(const float4*)(g_W1T + (size_t)(nblk * 128 + r) * HID + k0 + c4);
            Bs[r][c4 + 0] = v.x; Bs[r][c4 + 1] = v.y;
            Bs[r][c4 + 2] = v.z; Bs[r][c4 + 3] = v.w;
        }
        __syncthreads();

        #pragma unroll
        for (int kk = 0; kk < 4; kk++) {
            const int kb = kk * 8;
            uint32_t a[2][4];
            #pragma unroll
            for (int fm = 0; fm < 2; fm++) {
                int r0 = wm + fm * 16 + g;
                a[fm][0] = __float_as_uint(As[r0    ][kb + t]);
                a[fm][1] = __float_as_uint(As[r0 + 8][kb + t]);
                a[fm][2] = __float_as_uint(As[r0    ][kb + t + 4]);
                a[fm][3] = __float_as_uint(As[r0 + 8][kb + t + 4]);
            }
            #pragma unroll
            for (int nf = 0; nf < 8; nf++) {
                uint32_t b[2];
                int rn = wn + nf * 8 + g;
                b[0] = __float_as_uint(Bs[rn][kb + t]);
                b[1] = __float_as_uint(Bs[rn][kb + t + 4]);
                mma_tf32(acc[0][nf], a[0], b);
                mma_tf32(acc[1][nf], a[1], b);
            }
        }
        __syncthreads();
    }

    const int cbase = nblk * 128 + wn;
    #pragma unroll
    for (int fm = 0; fm < 2; fm++) {
        int row = bm + wm + fm * 16 + g;
        #pragma unroll
        for (int nf = 0; nf < 8; nf++) {
            int col = cbase + nf * 8 + 2 * t;
            float bv0 = __ldg(b1 + col), bv1 = __ldg(b1 + col + 1);
            if (row < NTOT)
                *(float2*)(g_x2 + (size_t)row * 256 + col) =
                    make_float2(acc[fm][nf][0] + bv0, acc[fm][nf][1] + bv1);
            if (row + 8 < NTOT)
                *(float2*)(g_x2 + (size_t)(row + 8) * 256 + col) =
                    make_float2(acc[fm][nf][2] + bv0, acc[fm][nf][3] + bv1);
        }
    }
}

// ---------------------------------------------------------------------------
// SpMM over row-sorted edges: Y[row] += val * X[col], warp per edge.
// ---------------------------------------------------------------------------
__global__ __launch_bounds__(256) void spmm_sorted(
    const float* __restrict__ X, float* __restrict__ Y)
{
    int e = blockIdx.x * 8 + (threadIdx.x >> 5);
    if (e >= N_EDGES) return;
    const int lane = threadIdx.x & 31;
    const int r = g_srow[e];
    const int c = g_scol[e];
    const float v = g_sval[e];
    const float* xp = X + (size_t)c * 256;
    float* yp = Y + (size_t)r * 256;
    #pragma unroll
    for (int j = 0; j < 8; j++)
        atomicAdd(yp + j * 32 + lane, v * __ldg(xp + j * 32 + lane));
}

// ---------------------------------------------------------------------------
extern "C" void kernel_launch(void* const* d_in, const int* in_sizes, int n_in,
                              void* d_out, int out_size)
{
    const float* user_feat = (const float*)d_in[0];
    const float* item_feat = (const float*)d_in[1];
    const int*   edge_rows = (const int*)  d_in[2];
    const int*   edge_cols = (const int*)  d_in[3];
    const float* edge_vals = (const float*)d_in[4];
    const float* W0        = (const float*)d_in[5];
    const float* b0        = (const float*)d_in[6];
    const float* Wres0     = (const float*)d_in[7];
    const float* W1        = (const float*)d_in[8];
    const float* b1        = (const float*)d_in[9];
    float* out = (float*)d_out;

    float* gx;  cudaGetSymbolAddress((void**)&gx,  g_x);
    float* gh;  cudaGetSymbolAddress((void**)&gh,  g_h);
    float* gx2; cudaGetSymbolAddress((void**)&gx2, g_x2);
    int* cnt;   cudaGetSymbolAddress((void**)&cnt,  g_cnt);
    int* cnt2;  cudaGetSymbolAddress((void**)&cnt2, g_cnt2);

    const int n_mtiles = (NTOT + 127) / 128;
    const int eb = (N_EDGES + 255) / 256;

    // --- edge sort chain (reused by both SpMMs) ---
    cudaMemsetAsync(cnt,  0, NBUCK * sizeof(int));
    cudaMemsetAsync(cnt2, 0, NBUCK * sizeof(int));
    edge_hist<<<eb, 256>>>(edge_rows);
    bucket_scan<<<1, 1024>>>();
    edge_scatter<<<eb, 256>>>(edge_rows, edge_cols, edge_vals);

    // weights -> K-major tf32 transposed copies
    transpose_weights<<<(HID * OUT_DIM + 255) / 256, 256>>>(W0, Wres0, W1);

    // Layer 0: x = feat@W0+b0 ; h = feat@Wres0
    gemm0_mma<<<dim3(n_mtiles, 4), 256>>>(user_feat, item_feat, b0);

    cudaMemsetAsync(d_out, 0, (size_t)NTOT * OUT_DIM * sizeof(float));

    // h += A @ x
    spmm_sorted<<<(N_EDGES + 7) / 8, 256>>>(gx, gh);

    // Layer 1: x2 = relu(h)@W1 + b1
    gemm1_mma<<<dim3(n_mtiles, 2), 256>>>(b1);

    // out = A @ x2
    spmm_sorted<<<(N_EDGES + 7) / 8, 256>>>(gx2, out);
}